// round 1
// baseline (speedup 1.0000x reference)
#include <cuda_runtime.h>
#include <math.h>

// Problem dims (fixed per reference)
#define BB    8
#define HH    64
#define WWID  64
#define CC    512
#define CFG   64
#define CHDIM 256
#define HW    4096          // HH*WWID
#define HWD   1024          // (HH/2)*(WWID/2)
#define MROWS 32768         // BB*HW
#define NPROJ 384           // CFG + CFG + CHDIM

// Scratch (device globals: allocation-free, BSS)
__device__ float d_proj[(size_t)MROWS * NPROJ];        // [B*hw, 384] = theta|phi|g pre-pool
__device__ float d_phi [(size_t)BB * HWD * CFG];       // pooled phi
__device__ float d_g   [(size_t)BB * HWD * CHDIM];     // pooled g
__device__ float d_s   [(size_t)BB * HWD * HW];        // s, then beta in-place (134 MB)
__device__ float d_o   [(size_t)MROWS * CHDIM];        // attention output pre-o3

// ---------------------------------------------------------------------------
// Kernel 1: fused projections. C[M,384] = X[M,512] @ [theta_w | phi_w | g_w] + bias
// 64x64 block tile, Ktile=16, 16x16 threads, 4x4 per-thread register tile.
// Column-tile -> source weight mapping is uniform per block (64-col aligned).
// ---------------------------------------------------------------------------
__global__ __launch_bounds__(256) void k_proj(const float* __restrict__ X,
    const float* __restrict__ tw, const float* __restrict__ tb,
    const float* __restrict__ pw, const float* __restrict__ pb,
    const float* __restrict__ gw, const float* __restrict__ gb)
{
    __shared__ float As[16][65];
    __shared__ float Bs[16][64];
    const int nb = blockIdx.x;              // 0..5 (col tile)
    const int mb = blockIdx.y;              // 0..511
    const float* Wp; const float* bp; int ldw, c0;
    if (nb == 0)      { Wp = tw; bp = tb; ldw = CFG;   c0 = 0; }
    else if (nb == 1) { Wp = pw; bp = pb; ldw = CFG;   c0 = 0; }
    else              { Wp = gw; bp = gb; ldw = CHDIM; c0 = (nb - 2) * 64; }
    const int row0 = mb * 64;
    const int tx = threadIdx.x, ty = threadIdx.y;
    const int t  = ty * 16 + tx;
    const int mm = t >> 2, kq = (t & 3) * 4;
    float acc[4][4] = {};
    for (int k0 = 0; k0 < CC; k0 += 16) {
        float4 va = *(const float4*)&X[(size_t)(row0 + mm) * CC + k0 + kq];
        As[kq + 0][mm] = va.x; As[kq + 1][mm] = va.y;
        As[kq + 2][mm] = va.z; As[kq + 3][mm] = va.w;
        #pragma unroll
        for (int i = 0; i < 4; i++) {
            int idx = i * 256 + t, kk = idx >> 6, nn = idx & 63;
            Bs[kk][nn] = Wp[(size_t)(k0 + kk) * ldw + c0 + nn];
        }
        __syncthreads();
        #pragma unroll
        for (int k = 0; k < 16; k++) {
            float a[4], b[4];
            #pragma unroll
            for (int i = 0; i < 4; i++) a[i] = As[k][ty * 4 + i];
            #pragma unroll
            for (int j = 0; j < 4; j++) b[j] = Bs[k][tx * 4 + j];
            #pragma unroll
            for (int i = 0; i < 4; i++)
                #pragma unroll
                for (int j = 0; j < 4; j++)
                    acc[i][j] = fmaf(a[i], b[j], acc[i][j]);
        }
        __syncthreads();
    }
    #pragma unroll
    for (int i = 0; i < 4; i++) {
        float4 v;
        v.x = acc[i][0] + bp[c0 + tx * 4 + 0];
        v.y = acc[i][1] + bp[c0 + tx * 4 + 1];
        v.z = acc[i][2] + bp[c0 + tx * 4 + 2];
        v.w = acc[i][3] + bp[c0 + tx * 4 + 3];
        *(float4*)&d_proj[(size_t)(row0 + ty * 4 + i) * NPROJ + nb * 64 + tx * 4] = v;
    }
}

// ---------------------------------------------------------------------------
// Kernel 2: 2x2 maxpool of phi (cols 64..127) and g (cols 128..383)
// ---------------------------------------------------------------------------
__global__ __launch_bounds__(256) void k_pool()
{
    const int TOT = BB * HWD * 320;
    int idx = blockIdx.x * 256 + threadIdx.x;
    if (idx >= TOT) return;
    int f = idx % 320;
    int i = (idx / 320) % HWD;
    int b = idx / (320 * HWD);
    int h = i >> 5, w = i & 31;
    int col = (f < CFG) ? (CFG + f) : (2 * CFG + (f - CFG));
    size_t rbase = ((size_t)b * HW + (size_t)(2 * h) * WWID + 2 * w) * NPROJ + col;
    float m = fmaxf(fmaxf(d_proj[rbase], d_proj[rbase + NPROJ]),
                    fmaxf(d_proj[rbase + (size_t)WWID * NPROJ],
                          d_proj[rbase + (size_t)(WWID + 1) * NPROJ]));
    if (f < CFG) d_phi[((size_t)b * HWD + i) * CFG + f] = m;
    else         d_g  [((size_t)b * HWD + i) * CHDIM + (f - CFG)] = m;
}

// ---------------------------------------------------------------------------
// Kernel 3: s[b,i,j] = sum_f phi[b,i,f] * theta[b,j,f]   (M=1024, N=4096, K=64)
// theta lives in d_proj cols [0,64), ld=384
// ---------------------------------------------------------------------------
__global__ __launch_bounds__(256) void k_s()
{
    __shared__ float As[16][65];
    __shared__ float Bs[16][65];
    const int jb = blockIdx.x, ib = blockIdx.y, b = blockIdx.z;
    const int j0 = jb * 64, i0 = ib * 64;
    const int tx = threadIdx.x, ty = threadIdx.y;
    const int t  = ty * 16 + tx;
    const int mm = t >> 2, kq = (t & 3) * 4;
    const float* phi = d_phi  + (size_t)b * HWD * CFG;
    const float* th  = d_proj + (size_t)b * HW * NPROJ;   // cols 0..63 = theta
    float acc[4][4] = {};
    for (int k0 = 0; k0 < CFG; k0 += 16) {
        float4 va = *(const float4*)&phi[(size_t)(i0 + mm) * CFG + k0 + kq];
        As[kq + 0][mm] = va.x; As[kq + 1][mm] = va.y;
        As[kq + 2][mm] = va.z; As[kq + 3][mm] = va.w;
        float4 vb = *(const float4*)&th[(size_t)(j0 + mm) * NPROJ + k0 + kq];
        Bs[kq + 0][mm] = vb.x; Bs[kq + 1][mm] = vb.y;
        Bs[kq + 2][mm] = vb.z; Bs[kq + 3][mm] = vb.w;
        __syncthreads();
        #pragma unroll
        for (int k = 0; k < 16; k++) {
            float a[4], bv[4];
            #pragma unroll
            for (int i = 0; i < 4; i++) a[i] = As[k][ty * 4 + i];
            #pragma unroll
            for (int j = 0; j < 4; j++) bv[j] = Bs[k][tx * 4 + j];
            #pragma unroll
            for (int i = 0; i < 4; i++)
                #pragma unroll
                for (int j = 0; j < 4; j++)
                    acc[i][j] = fmaf(a[i], bv[j], acc[i][j]);
        }
        __syncthreads();
    }
    #pragma unroll
    for (int i = 0; i < 4; i++) {
        float4 v = make_float4(acc[i][0], acc[i][1], acc[i][2], acc[i][3]);
        *(float4*)&d_s[((size_t)b * HWD + i0 + ty * 4 + i) * HW + j0 + tx * 4] = v;
    }
}

// ---------------------------------------------------------------------------
// Kernel 4: softmax over j (row length 4096). One block per (b,i) row; values
// kept in registers (16 per thread) so the row is read once, written once.
// ---------------------------------------------------------------------------
__global__ __launch_bounds__(256) void k_softmax()
{
    __shared__ float red[8];
    const size_t r = blockIdx.x;
    float* p = d_s + r * (size_t)HW;
    const int t = threadIdx.x;
    float v[16];
    #pragma unroll
    for (int i = 0; i < 16; i++) v[i] = p[i * 256 + t];
    float m = -1e30f;
    #pragma unroll
    for (int i = 0; i < 16; i++) m = fmaxf(m, v[i]);
    #pragma unroll
    for (int o = 16; o; o >>= 1) m = fmaxf(m, __shfl_xor_sync(0xffffffffu, m, o));
    if ((t & 31) == 0) red[t >> 5] = m;
    __syncthreads();
    float mx = fmaxf(fmaxf(fmaxf(red[0], red[1]), fmaxf(red[2], red[3])),
                     fmaxf(fmaxf(red[4], red[5]), fmaxf(red[6], red[7])));
    float s = 0.0f;
    #pragma unroll
    for (int i = 0; i < 16; i++) { v[i] = expf(v[i] - mx); s += v[i]; }
    #pragma unroll
    for (int o = 16; o; o >>= 1) s += __shfl_xor_sync(0xffffffffu, s, o);
    __syncthreads();
    if ((t & 31) == 0) red[t >> 5] = s;
    __syncthreads();
    float Z = (red[0] + red[1]) + (red[2] + red[3]) + (red[4] + red[5]) + (red[6] + red[7]);
    float inv = 1.0f / Z;
    #pragma unroll
    for (int i = 0; i < 16; i++) p[i * 256 + t] = v[i] * inv;
}

// ---------------------------------------------------------------------------
// Kernel 5: o[b,j,c] = sum_i beta[b,i,j] * g[b,i,c]   (M=4096, N=256, K=1024)
// beta accessed transposed: loads of beta[i, j0:j0+64] are contiguous -> coalesced
// ---------------------------------------------------------------------------
__global__ __launch_bounds__(256) void k_o()
{
    __shared__ float As[16][64];
    __shared__ float Bs[16][64];
    const int nb = blockIdx.x, mb = blockIdx.y, b = blockIdx.z;
    const int n0 = nb * 64, m0 = mb * 64;
    const int tx = threadIdx.x, ty = threadIdx.y;
    const int t  = ty * 16 + tx;
    const float* beta = d_s + (size_t)b * HWD * HW;
    const float* g    = d_g + (size_t)b * HWD * CHDIM;
    float acc[4][4] = {};
    for (int k0 = 0; k0 < HWD; k0 += 16) {
        #pragma unroll
        for (int i = 0; i < 4; i++) {
            int idx = i * 256 + t, kk = idx >> 6, nn = idx & 63;
            As[kk][nn] = beta[(size_t)(k0 + kk) * HW + m0 + nn];
            Bs[kk][nn] = g[(size_t)(k0 + kk) * CHDIM + n0 + nn];
        }
        __syncthreads();
        #pragma unroll
        for (int k = 0; k < 16; k++) {
            float a[4], bv[4];
            #pragma unroll
            for (int i = 0; i < 4; i++) a[i] = As[k][ty * 4 + i];
            float4 b4 = *(const float4*)&Bs[k][tx * 4];
            bv[0] = b4.x; bv[1] = b4.y; bv[2] = b4.z; bv[3] = b4.w;
            #pragma unroll
            for (int i = 0; i < 4; i++)
                #pragma unroll
                for (int j = 0; j < 4; j++)
                    acc[i][j] = fmaf(a[i], bv[j], acc[i][j]);
        }
        __syncthreads();
    }
    #pragma unroll
    for (int i = 0; i < 4; i++) {
        float4 v = make_float4(acc[i][0], acc[i][1], acc[i][2], acc[i][3]);
        *(float4*)&d_o[((size_t)b * HW + m0 + ty * 4 + i) * CHDIM + n0 + tx * 4] = v;
    }
}

// ---------------------------------------------------------------------------
// Kernel 6: out = gamma * (o @ o3_w + o3_b) + x   (M=32768, N=512, K=256)
// ---------------------------------------------------------------------------
__global__ __launch_bounds__(256) void k_final(const float* __restrict__ X,
    const float* __restrict__ ow, const float* __restrict__ ob,
    const float* __restrict__ gamma, float* __restrict__ out)
{
    __shared__ float As[16][65];
    __shared__ float Bs[16][64];
    const int nb = blockIdx.x, mb = blockIdx.y;
    const int col0 = nb * 64, row0 = mb * 64;
    const int tx = threadIdx.x, ty = threadIdx.y;
    const int t  = ty * 16 + tx;
    const int mm = t >> 2, kq = (t & 3) * 4;
    float acc[4][4] = {};
    for (int k0 = 0; k0 < CHDIM; k0 += 16) {
        float4 va = *(const float4*)&d_o[(size_t)(row0 + mm) * CHDIM + k0 + kq];
        As[kq + 0][mm] = va.x; As[kq + 1][mm] = va.y;
        As[kq + 2][mm] = va.z; As[kq + 3][mm] = va.w;
        #pragma unroll
        for (int i = 0; i < 4; i++) {
            int idx = i * 256 + t, kk = idx >> 6, nn = idx & 63;
            Bs[kk][nn] = ow[(size_t)(k0 + kk) * CC + col0 + nn];
        }
        __syncthreads();
        #pragma unroll
        for (int k = 0; k < 16; k++) {
            float a[4], bv[4];
            #pragma unroll
            for (int i = 0; i < 4; i++) a[i] = As[k][ty * 4 + i];
            float4 b4 = *(const float4*)&Bs[k][tx * 4];
            bv[0] = b4.x; bv[1] = b4.y; bv[2] = b4.z; bv[3] = b4.w;
            #pragma unroll
            for (int i = 0; i < 4; i++)
                #pragma unroll
                for (int j = 0; j < 4; j++)
                    acc[i][j] = fmaf(a[i], bv[j], acc[i][j]);
        }
        __syncthreads();
    }
    const float gma = gamma[0];
    float4 bias = *(const float4*)&ob[col0 + tx * 4];
    #pragma unroll
    for (int i = 0; i < 4; i++) {
        size_t off = (size_t)(row0 + ty * 4 + i) * CC + col0 + tx * 4;
        float4 xv = *(const float4*)&X[off];
        float4 v;
        v.x = gma * (acc[i][0] + bias.x) + xv.x;
        v.y = gma * (acc[i][1] + bias.y) + xv.y;
        v.z = gma * (acc[i][2] + bias.z) + xv.z;
        v.w = gma * (acc[i][3] + bias.w) + xv.w;
        *(float4*)&out[off] = v;
    }
}

// ---------------------------------------------------------------------------
extern "C" void kernel_launch(void* const* d_in, const int* in_sizes, int n_in,
                              void* d_out, int out_size)
{
    const float* x  = (const float*)d_in[0];
    const float* tw = (const float*)d_in[1];
    const float* tb = (const float*)d_in[2];
    const float* pw = (const float*)d_in[3];
    const float* pb = (const float*)d_in[4];
    const float* gw = (const float*)d_in[5];
    const float* gb = (const float*)d_in[6];
    const float* ow = (const float*)d_in[7];
    const float* ob = (const float*)d_in[8];
    const float* gm = (const float*)d_in[9];
    float* out = (float*)d_out;

    dim3 blk(16, 16);
    k_proj   <<<dim3(6, 512), blk>>>(x, tw, tb, pw, pb, gw, gb);
    k_pool   <<<(BB * HWD * 320 + 255) / 256, 256>>>();
    k_s      <<<dim3(64, 16, 8), blk>>>();
    k_softmax<<<BB * HWD, 256>>>();
    k_o      <<<dim3(4, 64, 8), blk>>>();
    k_final  <<<dim3(8, 512), blk>>>(x, ow, ob, gm, out);
}

// round 2
// speedup vs baseline: 4.5317x; 4.5317x over previous
#include <cuda_runtime.h>
#include <cuda_bf16.h>
#include <math.h>

// Problem dims (fixed)
#define BB    8
#define HH    64
#define WWID  64
#define CC    512
#define CFG   64
#define CHDIM 256
#define HW    4096
#define HWD   1024
#define MROWS 32768          // BB*HW
#define NPROJ 384            // CFG + CFG + CHDIM

typedef __nv_bfloat16 bf16;
typedef __nv_bfloat162 bf162;

// -------------------- device scratch (BSS, allocation-free) ----------------
__device__ bf16  d_xbf  [(size_t)MROWS * CC];         // x in bf16
__device__ bf16  d_wcat [(size_t)CC * NPROJ];         // [theta|phi|g] weights
__device__ bf16  d_owbf [(size_t)CHDIM * CC];         // o3 weights
__device__ float d_bcat [NPROJ];                      // [theta|phi|g] biases
__device__ bf16  d_projbf[(size_t)MROWS * NPROJ];     // projections pre-pool
__device__ bf16  d_phibf[(size_t)BB * HWD * CFG];
__device__ bf16  d_gbf  [(size_t)BB * HWD * CHDIM];
__device__ float d_s    [(size_t)BB * HWD * HW];      // logits fp32
__device__ bf16  d_betabf[(size_t)BB * HWD * HW];     // softmax out bf16
__device__ bf16  d_obf  [(size_t)MROWS * CHDIM];      // attention out

// -------------------- PTX helpers -----------------------------------------
__device__ __forceinline__ unsigned smem_u32(const void* p) {
    return (unsigned)__cvta_generic_to_shared(p);
}
__device__ __forceinline__ void ldsm_x4(unsigned a[4], unsigned addr) {
    asm volatile("ldmatrix.sync.aligned.m8n8.x4.shared.b16 {%0,%1,%2,%3}, [%4];"
        : "=r"(a[0]), "=r"(a[1]), "=r"(a[2]), "=r"(a[3]) : "r"(addr));
}
__device__ __forceinline__ void ldsm_x4_t(unsigned a[4], unsigned addr) {
    asm volatile("ldmatrix.sync.aligned.m8n8.x4.trans.shared.b16 {%0,%1,%2,%3}, [%4];"
        : "=r"(a[0]), "=r"(a[1]), "=r"(a[2]), "=r"(a[3]) : "r"(addr));
}
__device__ __forceinline__ void ldsm_x2(unsigned b[2], unsigned addr) {
    asm volatile("ldmatrix.sync.aligned.m8n8.x2.shared.b16 {%0,%1}, [%2];"
        : "=r"(b[0]), "=r"(b[1]) : "r"(addr));
}
__device__ __forceinline__ void ldsm_x2_t(unsigned b[2], unsigned addr) {
    asm volatile("ldmatrix.sync.aligned.m8n8.x2.trans.shared.b16 {%0,%1}, [%2];"
        : "=r"(b[0]), "=r"(b[1]) : "r"(addr));
}
__device__ __forceinline__ void mma16816(float c[4], const unsigned a[4], const unsigned b[2]) {
    asm volatile(
        "mma.sync.aligned.m16n8k16.row.col.f32.bf16.bf16.f32 "
        "{%0,%1,%2,%3}, {%4,%5,%6,%7}, {%8,%9}, {%0,%1,%2,%3};"
        : "+f"(c[0]), "+f"(c[1]), "+f"(c[2]), "+f"(c[3])
        : "r"(a[0]), "r"(a[1]), "r"(a[2]), "r"(a[3]), "r"(b[0]), "r"(b[1]));
}

// -------------------- epilogue functors ------------------------------------
struct EpiProj {  // bf16 out, add bias from d_bcat
    __device__ void operator()(int, int r, int c, float v0, float v1) const {
        bf162 p;
        p.x = __float2bfloat16(v0 + d_bcat[c]);
        p.y = __float2bfloat16(v1 + d_bcat[c + 1]);
        *(bf162*)&d_projbf[(size_t)r * NPROJ + c] = p;
    }
};
struct EpiS {     // fp32 logits
    __device__ void operator()(int b, int r, int c, float v0, float v1) const {
        *(float2*)&d_s[((size_t)b * HWD + r) * HW + c] = make_float2(v0, v1);
    }
};
struct EpiO {     // bf16 attention out
    __device__ void operator()(int b, int r, int c, float v0, float v1) const {
        bf162 p; p.x = __float2bfloat16(v0); p.y = __float2bfloat16(v1);
        *(bf162*)&d_obf[((size_t)b * HW + r) * CHDIM + c] = p;
    }
};
struct EpiFinal { // out = gamma*(acc+bias) + x, fp32
    const float* x; const float* ob; const float* gm; float* out;
    __device__ void operator()(int, int r, int c, float v0, float v1) const {
        float g = gm[0];
        size_t off = (size_t)r * CC + c;
        float2 xv = *(const float2*)&x[off];
        float2 o;
        o.x = g * (v0 + ob[c])     + xv.x;
        o.y = g * (v1 + ob[c + 1]) + xv.y;
        *(float2*)&out[off] = o;
    }
};

// -------------------- templated bf16 GEMM ----------------------------------
// C[M,N] (+epi) = A @ B.  Block tile 128x128x32, 8 warps (2x4), warp 64x32.
// AKM=false: A[m][k] (k contig).  AKM=true: A[k][m] (m contig)  [beta case]
// BNK=false: B[k][n] (n contig).  BNK=true: B[n][k] (k contig)  [theta case]
// All dims must divide tiles exactly (they do for this problem).
template<bool AKM, bool BNK, class Epi>
__global__ __launch_bounds__(256, 2) void gemm_bf16(
    const bf16* __restrict__ A, const bf16* __restrict__ B,
    int lda, int ldb, int K, size_t bsA, size_t bsB, Epi epi)
{
    constexpr int AST = AKM ? 136 : 40;   // smem row stride (halves), padded
    constexpr int ASZ = AKM ? 32 * 136 : 128 * 40;
    constexpr int BST = BNK ? 40 : 136;
    constexpr int BSZ = BNK ? 128 * 40 : 32 * 136;
    __shared__ __align__(16) bf16 As[ASZ];
    __shared__ __align__(16) bf16 Bs[BSZ];

    const int bz = blockIdx.z;
    A += (size_t)bz * bsA;
    B += (size_t)bz * bsB;
    const int m0 = blockIdx.y * 128, n0 = blockIdx.x * 128;

    const int t = threadIdx.x;
    const unsigned lane = t & 31;
    const int w = t >> 5;
    const int wm0 = (w >> 2) * 64;     // warp row offset in tile
    const int wn0 = (w & 3) * 32;      // warp col offset in tile

    uint4 ra[2], rb[2];
    auto ldA = [&](int k0) {
        #pragma unroll
        for (int it = 0; it < 2; it++) {
            int e = it * 256 + t;
            if (!AKM) { int r = e >> 2, c = (e & 3) << 3;
                ra[it] = *(const uint4*)(A + (size_t)(m0 + r) * lda + k0 + c); }
            else      { int r = e >> 4, c = (e & 15) << 3;
                ra[it] = *(const uint4*)(A + (size_t)(k0 + r) * lda + m0 + c); }
        }
    };
    auto ldB = [&](int k0) {
        #pragma unroll
        for (int it = 0; it < 2; it++) {
            int e = it * 256 + t;
            if (BNK) { int r = e >> 2, c = (e & 3) << 3;
                rb[it] = *(const uint4*)(B + (size_t)(n0 + r) * ldb + k0 + c); }
            else     { int r = e >> 4, c = (e & 15) << 3;
                rb[it] = *(const uint4*)(B + (size_t)(k0 + r) * ldb + n0 + c); }
        }
    };
    auto stAB = [&]() {
        #pragma unroll
        for (int it = 0; it < 2; it++) {
            int e = it * 256 + t;
            if (!AKM) { int r = e >> 2, c = (e & 3) << 3; *(uint4*)&As[r * 40 + c] = ra[it]; }
            else      { int r = e >> 4, c = (e & 15) << 3; *(uint4*)&As[r * 136 + c] = ra[it]; }
            if (BNK)  { int r = e >> 2, c = (e & 3) << 3; *(uint4*)&Bs[r * 40 + c] = rb[it]; }
            else      { int r = e >> 4, c = (e & 15) << 3; *(uint4*)&Bs[r * 136 + c] = rb[it]; }
        }
    };

    float cc[4][4][4] = {};
    const unsigned asb = smem_u32(As), bsb = smem_u32(Bs);

    ldA(0); ldB(0);
    stAB();
    __syncthreads();

    for (int k0 = 0; k0 < K; k0 += 32) {
        const bool more = (k0 + 32 < K);
        if (more) { ldA(k0 + 32); ldB(k0 + 32); }

        #pragma unroll
        for (int ks = 0; ks < 2; ks++) {
            const int kk = ks * 16;
            unsigned afr[4][4];
            #pragma unroll
            for (int mi = 0; mi < 4; mi++) {
                unsigned addr;
                if (!AKM) {
                    addr = asb + (unsigned)(((wm0 + mi * 16 + (lane & 15)) * AST
                                  + kk + ((lane >> 4) << 3)) * 2);
                    ldsm_x4(afr[mi], addr);
                } else {
                    addr = asb + (unsigned)(((kk + (lane & 7) + ((lane >> 4) << 3)) * AST
                                  + wm0 + mi * 16 + (((lane >> 3) & 1) << 3)) * 2);
                    ldsm_x4_t(afr[mi], addr);
                }
            }
            unsigned bfr[4][2];
            #pragma unroll
            for (int ni = 0; ni < 4; ni++) {
                unsigned addr;
                if (!BNK) {
                    addr = bsb + (unsigned)(((kk + (lane & 15)) * BST + wn0 + ni * 8) * 2);
                    ldsm_x2_t(bfr[ni], addr);
                } else {
                    addr = bsb + (unsigned)(((wn0 + ni * 8 + (lane & 7)) * BST
                                  + kk + (((lane >> 3) & 1) << 3)) * 2);
                    ldsm_x2(bfr[ni], addr);
                }
            }
            #pragma unroll
            for (int mi = 0; mi < 4; mi++)
                #pragma unroll
                for (int ni = 0; ni < 4; ni++)
                    mma16816(cc[mi][ni], afr[mi], bfr[ni]);
        }

        __syncthreads();
        if (more) { stAB(); __syncthreads(); }
    }

    // epilogue
    #pragma unroll
    for (int mi = 0; mi < 4; mi++)
        #pragma unroll
        for (int ni = 0; ni < 4; ni++) {
            int r  = m0 + wm0 + mi * 16 + (int)(lane >> 2);
            int ci = n0 + wn0 + ni * 8 + (int)((lane & 3) << 1);
            epi(bz, r,     ci, cc[mi][ni][0], cc[mi][ni][1]);
            epi(bz, r + 8, ci, cc[mi][ni][2], cc[mi][ni][3]);
        }
}

// -------------------- prep kernels -----------------------------------------
__global__ __launch_bounds__(256) void k_cvt_x(const float* __restrict__ x) {
    size_t i = ((size_t)blockIdx.x * 256 + threadIdx.x) * 4;
    float4 v = *(const float4*)&x[i];
    bf162 p0, p1;
    p0.x = __float2bfloat16(v.x); p0.y = __float2bfloat16(v.y);
    p1.x = __float2bfloat16(v.z); p1.y = __float2bfloat16(v.w);
    *(bf162*)&d_xbf[i]     = p0;
    *(bf162*)&d_xbf[i + 2] = p1;
}

__global__ __launch_bounds__(256) void k_cvt_w(
    const float* __restrict__ tw, const float* __restrict__ pw, const float* __restrict__ gw,
    const float* __restrict__ tb, const float* __restrict__ pb, const float* __restrict__ gb,
    const float* __restrict__ ow)
{
    int i = blockIdx.x * 256 + threadIdx.x;
    const int W1 = CC * NPROJ, W2 = W1 + CHDIM * CC;
    if (i < W1) {
        int r = i / NPROJ, c = i % NPROJ;
        float v = (c < 64) ? tw[r * 64 + c] : (c < 128) ? pw[r * 64 + c - 64]
                                            : gw[r * 256 + c - 128];
        d_wcat[i] = __float2bfloat16(v);
    } else if (i < W2) {
        int j = i - W1;
        d_owbf[j] = __float2bfloat16(ow[j]);
    } else if (i < W2 + NPROJ) {
        int c = i - W2;
        d_bcat[c] = (c < 64) ? tb[c] : (c < 128) ? pb[c - 64] : gb[c - 128];
    }
}

// -------------------- 2x2 maxpool of phi+g (bf16) ---------------------------
__global__ __launch_bounds__(256) void k_pool2() {
    int idx = blockIdx.x * 256 + threadIdx.x;     // over BB*HWD*160 pairs
    if (idx >= BB * HWD * 160) return;
    int fp = idx % 160;
    int i  = (idx / 160) % HWD;
    int b  = idx / (160 * HWD);
    int h = i >> 5, w = i & 31;
    int col = 64 + fp * 2;                         // phi cols 64..127, g cols 128..383
    size_t rb = ((size_t)b * HW + (size_t)(2 * h) * WWID + 2 * w) * NPROJ + col;
    bf162 v0 = *(const bf162*)&d_projbf[rb];
    bf162 v1 = *(const bf162*)&d_projbf[rb + NPROJ];
    bf162 v2 = *(const bf162*)&d_projbf[rb + (size_t)WWID * NPROJ];
    bf162 v3 = *(const bf162*)&d_projbf[rb + (size_t)(WWID + 1) * NPROJ];
    float mx = fmaxf(fmaxf(__bfloat162float(v0.x), __bfloat162float(v1.x)),
                     fmaxf(__bfloat162float(v2.x), __bfloat162float(v3.x)));
    float my = fmaxf(fmaxf(__bfloat162float(v0.y), __bfloat162float(v1.y)),
                     fmaxf(__bfloat162float(v2.y), __bfloat162float(v3.y)));
    bf162 o; o.x = __float2bfloat16(mx); o.y = __float2bfloat16(my);
    int f0 = fp * 2;
    if (f0 < 64) *(bf162*)&d_phibf[((size_t)b * HWD + i) * CFG + f0] = o;
    else         *(bf162*)&d_gbf  [((size_t)b * HWD + i) * CHDIM + (f0 - 64)] = o;
}

// -------------------- softmax over j (row 4096), fp32 in / bf16 out ---------
__global__ __launch_bounds__(256) void k_softmax() {
    __shared__ float red[8];
    const size_t r = blockIdx.x;
    const float* p = d_s + r * (size_t)HW;
    bf16* q = d_betabf + r * (size_t)HW;
    const int t = threadIdx.x;
    float v[16];
    #pragma unroll
    for (int i = 0; i < 16; i++) v[i] = p[i * 256 + t];
    float m = -1e30f;
    #pragma unroll
    for (int i = 0; i < 16; i++) m = fmaxf(m, v[i]);
    #pragma unroll
    for (int o = 16; o; o >>= 1) m = fmaxf(m, __shfl_xor_sync(0xffffffffu, m, o));
    if ((t & 31) == 0) red[t >> 5] = m;
    __syncthreads();
    float mx = fmaxf(fmaxf(fmaxf(red[0], red[1]), fmaxf(red[2], red[3])),
                     fmaxf(fmaxf(red[4], red[5]), fmaxf(red[6], red[7])));
    float s = 0.0f;
    #pragma unroll
    for (int i = 0; i < 16; i++) { v[i] = expf(v[i] - mx); s += v[i]; }
    #pragma unroll
    for (int o = 16; o; o >>= 1) s += __shfl_xor_sync(0xffffffffu, s, o);
    __syncthreads();
    if ((t & 31) == 0) red[t >> 5] = s;
    __syncthreads();
    float Z = (red[0] + red[1]) + (red[2] + red[3]) + (red[4] + red[5]) + (red[6] + red[7]);
    float inv = 1.0f / Z;
    #pragma unroll
    for (int i = 0; i < 16; i++) q[i * 256 + t] = __float2bfloat16(v[i] * inv);
}

// -------------------- launch -----------------------------------------------
extern "C" void kernel_launch(void* const* d_in, const int* in_sizes, int n_in,
                              void* d_out, int out_size)
{
    const float* x  = (const float*)d_in[0];
    const float* tw = (const float*)d_in[1];
    const float* tb = (const float*)d_in[2];
    const float* pw = (const float*)d_in[3];
    const float* pb = (const float*)d_in[4];
    const float* gw = (const float*)d_in[5];
    const float* gb = (const float*)d_in[6];
    const float* ow = (const float*)d_in[7];
    const float* ob = (const float*)d_in[8];
    const float* gm = (const float*)d_in[9];
    float* out = (float*)d_out;

    void *p_xbf, *p_wcat, *p_owbf, *p_projbf, *p_phibf, *p_gbf, *p_betabf, *p_obf;
    cudaGetSymbolAddress(&p_xbf,   d_xbf);
    cudaGetSymbolAddress(&p_wcat,  d_wcat);
    cudaGetSymbolAddress(&p_owbf,  d_owbf);
    cudaGetSymbolAddress(&p_projbf,d_projbf);
    cudaGetSymbolAddress(&p_phibf, d_phibf);
    cudaGetSymbolAddress(&p_gbf,   d_gbf);
    cudaGetSymbolAddress(&p_betabf,d_betabf);
    cudaGetSymbolAddress(&p_obf,   d_obf);

    // prep: convert x and weights to bf16
    k_cvt_x<<<(int)(((size_t)MROWS * CC / 4) / 256), 256>>>(x);
    k_cvt_w<<<(CC * NPROJ + CHDIM * CC + NPROJ + 255) / 256, 256>>>(tw, pw, gw, tb, pb, gb, ow);

    // 1) projections: [32768,512] @ [512,384]
    gemm_bf16<false, false, EpiProj><<<dim3(NPROJ / 128, MROWS / 128, 1), 256>>>(
        (const bf16*)p_xbf, (const bf16*)p_wcat, CC, NPROJ, CC, 0, 0, EpiProj{});

    // 2) 2x2 maxpool
    k_pool2<<<(BB * HWD * 160 + 255) / 256, 256>>>();

    // 3) s = phi @ theta^T per batch: [1024,64] @ [64,4096]
    gemm_bf16<false, true, EpiS><<<dim3(HW / 128, HWD / 128, BB), 256>>>(
        (const bf16*)p_phibf, (const bf16*)p_projbf, CFG, NPROJ, CFG,
        (size_t)HWD * CFG, (size_t)HW * NPROJ, EpiS{});

    // 4) softmax rows
    k_softmax<<<BB * HWD, 256>>>();

    // 5) o = beta^T @ g per batch: [4096,1024] @ [1024,256], A is [k][m]
    gemm_bf16<true, false, EpiO><<<dim3(CHDIM / 128, HW / 128, BB), 256>>>(
        (const bf16*)p_betabf, (const bf16*)p_gbf, HW, CHDIM, HWD,
        (size_t)HWD * HW, (size_t)HWD * CHDIM, EpiO{});

    // 6) out = gamma*(o @ o3_w + b) + x: [32768,256] @ [256,512]
    EpiFinal ef{x, ob, gm, out};
    gemm_bf16<false, false, EpiFinal><<<dim3(CC / 128, MROWS / 128, 1), 256>>>(
        (const bf16*)p_obf, (const bf16*)p_owbf, CHDIM, CC, CHDIM, 0, 0, ef);
}

// round 3
// speedup vs baseline: 4.8192x; 1.0634x over previous
#include <cuda_runtime.h>
#include <cuda_bf16.h>
#include <math.h>

// Problem dims (fixed)
#define BB    8
#define HH    64
#define WWID  64
#define CC    512
#define CFG   64
#define CHDIM 256
#define HW    4096
#define HWD   1024
#define MROWS 32768          // BB*HW
#define NPROJ 384            // CFG + CFG + CHDIM

typedef __nv_bfloat16 bf16;
typedef __nv_bfloat162 bf162;

// -------------------- device scratch (BSS, allocation-free) ----------------
__device__ bf16  d_wcat [(size_t)CC * NPROJ];         // [theta|phi|g] weights
__device__ bf16  d_owbf [(size_t)CHDIM * CC];         // o3 weights
__device__ float d_bcat [NPROJ];                      // [theta|phi|g] biases
__device__ bf16  d_projbf[(size_t)MROWS * NPROJ];     // projections pre-pool
__device__ bf16  d_phibf[(size_t)BB * HWD * CFG];
__device__ bf16  d_gbf  [(size_t)BB * HWD * CHDIM];   // pooled g, later scaled by 1/Z
__device__ bf16  d_ebf  [(size_t)BB * HWD * HW];      // e = exp(s), unnormalized
__device__ float d_part [(size_t)BB * HWD * 32];      // per-(row, jtile) partial sums
__device__ float d_invZ [(size_t)BB * HWD];           // 1/Z per softmax row
__device__ bf16  d_obf  [(size_t)MROWS * CHDIM];      // attention out

// -------------------- PTX helpers -----------------------------------------
__device__ __forceinline__ unsigned smem_u32(const void* p) {
    return (unsigned)__cvta_generic_to_shared(p);
}
__device__ __forceinline__ void ldsm_x4(unsigned a[4], unsigned addr) {
    asm volatile("ldmatrix.sync.aligned.m8n8.x4.shared.b16 {%0,%1,%2,%3}, [%4];"
        : "=r"(a[0]), "=r"(a[1]), "=r"(a[2]), "=r"(a[3]) : "r"(addr));
}
__device__ __forceinline__ void ldsm_x4_t(unsigned a[4], unsigned addr) {
    asm volatile("ldmatrix.sync.aligned.m8n8.x4.trans.shared.b16 {%0,%1,%2,%3}, [%4];"
        : "=r"(a[0]), "=r"(a[1]), "=r"(a[2]), "=r"(a[3]) : "r"(addr));
}
__device__ __forceinline__ void ldsm_x2(unsigned b[2], unsigned addr) {
    asm volatile("ldmatrix.sync.aligned.m8n8.x2.shared.b16 {%0,%1}, [%2];"
        : "=r"(b[0]), "=r"(b[1]) : "r"(addr));
}
__device__ __forceinline__ void ldsm_x2_t(unsigned b[2], unsigned addr) {
    asm volatile("ldmatrix.sync.aligned.m8n8.x2.trans.shared.b16 {%0,%1}, [%2];"
        : "=r"(b[0]), "=r"(b[1]) : "r"(addr));
}
__device__ __forceinline__ void mma16816(float c[4], const unsigned a[4], const unsigned b[2]) {
    asm volatile(
        "mma.sync.aligned.m16n8k16.row.col.f32.bf16.bf16.f32 "
        "{%0,%1,%2,%3}, {%4,%5,%6,%7}, {%8,%9}, {%0,%1,%2,%3};"
        : "+f"(c[0]), "+f"(c[1]), "+f"(c[2]), "+f"(c[3])
        : "r"(a[0]), "r"(a[1]), "r"(a[2]), "r"(a[3]), "r"(b[0]), "r"(b[1]));
}

// -------------------- epilogue functors ------------------------------------
struct EpiNone {
    __device__ void operator()(int, int, int, float, float) const {}
};
struct EpiProj {  // bf16 out, add bias from d_bcat
    __device__ void operator()(int, int r, int c, float v0, float v1) const {
        bf162 p;
        p.x = __float2bfloat16(v0 + d_bcat[c]);
        p.y = __float2bfloat16(v1 + d_bcat[c + 1]);
        *(bf162*)&d_projbf[(size_t)r * NPROJ + c] = p;
    }
};
struct EpiO {     // bf16 attention out
    __device__ void operator()(int b, int r, int c, float v0, float v1) const {
        bf162 p; p.x = __float2bfloat16(v0); p.y = __float2bfloat16(v1);
        *(bf162*)&d_obf[((size_t)b * HW + r) * CHDIM + c] = p;
    }
};
struct EpiFinal { // out = gamma*(acc+bias) + x, fp32
    const float* x; const float* ob; const float* gm; float* out;
    __device__ void operator()(int, int r, int c, float v0, float v1) const {
        float g = gm[0];
        size_t off = (size_t)r * CC + c;
        float2 xv = *(const float2*)&x[off];
        float2 o;
        o.x = g * (v0 + ob[c])     + xv.x;
        o.y = g * (v1 + ob[c + 1]) + xv.y;
        *(float2*)&out[off] = o;
    }
};

// -------------------- templated bf16 GEMM ----------------------------------
// C[M,N] (+epi) = A @ B.  Block tile 128x128x32, 8 warps (2x4), warp 64x32.
// AKM=false: A[m][k] (k contig).  AKM=true: A[k][m] (m contig).
// BNK=false: B[k][n] (n contig).  BNK=true: B[n][k] (k contig).
// AF32: A is fp32 in gmem (MK layout only), converted to bf16 into smem.
// SEPI: softmax-exp epilogue (writes e=exp(acc) bf16 to d_ebf + row partials).
template<bool AKM, bool BNK, bool AF32, bool SEPI, class Epi>
__global__ __launch_bounds__(256, 2) void gemm_bf16(
    const void* __restrict__ Av, const bf16* __restrict__ B,
    int lda, int ldb, int K, size_t bsA, size_t bsB, Epi epi)
{
    constexpr int AST = AKM ? 136 : 40;   // smem row stride (halves), padded
    constexpr int ASZ = AKM ? 32 * 136 : 128 * 40;
    constexpr int BST = BNK ? 40 : 136;
    constexpr int BSZ = BNK ? 128 * 40 : 32 * 136;
    __shared__ __align__(16) bf16 As[ASZ];
    __shared__ __align__(16) bf16 Bs[BSZ];
    __shared__ float rs[128][4];          // SEPI row partial sums

    const bf16*  A   = (const bf16*)Av;
    const float* A32 = (const float*)Av;
    const int bz = blockIdx.z;
    A   += (size_t)bz * bsA;
    B   += (size_t)bz * bsB;
    const int m0 = blockIdx.y * 128, n0 = blockIdx.x * 128;

    const int t = threadIdx.x;
    const unsigned lane = t & 31;
    const int w = t >> 5;
    const int wm0 = (w >> 2) * 64;     // warp row offset in tile
    const int wn0 = (w & 3) * 32;      // warp col offset in tile

    uint4 ra[2], rb[2];
    auto ldA = [&](int k0) {
        #pragma unroll
        for (int it = 0; it < 2; it++) {
            int e = it * 256 + t;
            if (AF32) {
                int r = e >> 2, c = (e & 3) << 3;
                const float* p = A32 + (size_t)(m0 + r) * lda + k0 + c;
                float4 f0 = *(const float4*)p;
                float4 f1 = *(const float4*)(p + 4);
                bf162 h0 = __float22bfloat162_rn(make_float2(f0.x, f0.y));
                bf162 h1 = __float22bfloat162_rn(make_float2(f0.z, f0.w));
                bf162 h2 = __float22bfloat162_rn(make_float2(f1.x, f1.y));
                bf162 h3 = __float22bfloat162_rn(make_float2(f1.z, f1.w));
                ra[it].x = *(unsigned*)&h0; ra[it].y = *(unsigned*)&h1;
                ra[it].z = *(unsigned*)&h2; ra[it].w = *(unsigned*)&h3;
            } else if (!AKM) {
                int r = e >> 2, c = (e & 3) << 3;
                ra[it] = *(const uint4*)(A + (size_t)(m0 + r) * lda + k0 + c);
            } else {
                int r = e >> 4, c = (e & 15) << 3;
                ra[it] = *(const uint4*)(A + (size_t)(k0 + r) * lda + m0 + c);
            }
        }
    };
    auto ldB = [&](int k0) {
        #pragma unroll
        for (int it = 0; it < 2; it++) {
            int e = it * 256 + t;
            if (BNK) { int r = e >> 2, c = (e & 3) << 3;
                rb[it] = *(const uint4*)(B + (size_t)(n0 + r) * ldb + k0 + c); }
            else     { int r = e >> 4, c = (e & 15) << 3;
                rb[it] = *(const uint4*)(B + (size_t)(k0 + r) * ldb + n0 + c); }
        }
    };
    auto stAB = [&]() {
        #pragma unroll
        for (int it = 0; it < 2; it++) {
            int e = it * 256 + t;
            if (!AKM) { int r = e >> 2, c = (e & 3) << 3; *(uint4*)&As[r * 40 + c] = ra[it]; }
            else      { int r = e >> 4, c = (e & 15) << 3; *(uint4*)&As[r * 136 + c] = ra[it]; }
            if (BNK)  { int r = e >> 2, c = (e & 3) << 3; *(uint4*)&Bs[r * 40 + c] = rb[it]; }
            else      { int r = e >> 4, c = (e & 15) << 3; *(uint4*)&Bs[r * 136 + c] = rb[it]; }
        }
    };

    float cc[4][4][4] = {};
    const unsigned asb = smem_u32(As), bsb = smem_u32(Bs);

    ldA(0); ldB(0);
    stAB();
    __syncthreads();

    for (int k0 = 0; k0 < K; k0 += 32) {
        const bool more = (k0 + 32 < K);
        if (more) { ldA(k0 + 32); ldB(k0 + 32); }

        #pragma unroll
        for (int ks = 0; ks < 2; ks++) {
            const int kk = ks * 16;
            unsigned afr[4][4];
            #pragma unroll
            for (int mi = 0; mi < 4; mi++) {
                unsigned addr;
                if (!AKM) {
                    addr = asb + (unsigned)(((wm0 + mi * 16 + (lane & 15)) * AST
                                  + kk + ((lane >> 4) << 3)) * 2);
                    ldsm_x4(afr[mi], addr);
                } else {
                    addr = asb + (unsigned)(((kk + (lane & 7) + ((lane >> 4) << 3)) * AST
                                  + wm0 + mi * 16 + (((lane >> 3) & 1) << 3)) * 2);
                    ldsm_x4_t(afr[mi], addr);
                }
            }
            unsigned bfr[4][2];
            #pragma unroll
            for (int ni = 0; ni < 4; ni++) {
                unsigned addr;
                if (!BNK) {
                    addr = bsb + (unsigned)(((kk + (lane & 15)) * BST + wn0 + ni * 8) * 2);
                    ldsm_x2_t(bfr[ni], addr);
                } else {
                    addr = bsb + (unsigned)(((wn0 + ni * 8 + (lane & 7)) * BST
                                  + kk + (((lane >> 3) & 1) << 3)) * 2);
                    ldsm_x2(bfr[ni], addr);
                }
            }
            #pragma unroll
            for (int mi = 0; mi < 4; mi++)
                #pragma unroll
                for (int ni = 0; ni < 4; ni++)
                    mma16816(cc[mi][ni], afr[mi], bfr[ni]);
        }

        __syncthreads();
        if (more) { stAB(); __syncthreads(); }
    }

    if constexpr (SEPI) {
        // e = exp(acc), write bf16, accumulate deterministic row partial sums
        #pragma unroll
        for (int mi = 0; mi < 4; mi++) {
            float rp0 = 0.f, rp1 = 0.f;
            const int r = m0 + wm0 + mi * 16 + (int)(lane >> 2);
            #pragma unroll
            for (int ni = 0; ni < 4; ni++) {
                const int ci = n0 + wn0 + ni * 8 + (int)((lane & 3) << 1);
                float e0 = __expf(cc[mi][ni][0]), e1 = __expf(cc[mi][ni][1]);
                float e2 = __expf(cc[mi][ni][2]), e3 = __expf(cc[mi][ni][3]);
                bf162 p; p.x = __float2bfloat16(e0); p.y = __float2bfloat16(e1);
                *(bf162*)&d_ebf[((size_t)bz * HWD + r) * HW + ci] = p;
                bf162 q; q.x = __float2bfloat16(e2); q.y = __float2bfloat16(e3);
                *(bf162*)&d_ebf[((size_t)bz * HWD + r + 8) * HW + ci] = q;
                rp0 += e0 + e1; rp1 += e2 + e3;
            }
            rp0 += __shfl_xor_sync(0xffffffffu, rp0, 1);
            rp0 += __shfl_xor_sync(0xffffffffu, rp0, 2);
            rp1 += __shfl_xor_sync(0xffffffffu, rp1, 1);
            rp1 += __shfl_xor_sync(0xffffffffu, rp1, 2);
            if ((lane & 3) == 0) {
                int rl = wm0 + mi * 16 + (int)(lane >> 2);
                rs[rl][w & 3]     = rp0;
                rs[rl + 8][w & 3] = rp1;
            }
        }
        __syncthreads();
        if (t < 128) {
            float z = (rs[t][0] + rs[t][1]) + (rs[t][2] + rs[t][3]);
            d_part[((size_t)bz * HWD + m0 + t) * 32 + blockIdx.x] = z;
        }
    } else {
        #pragma unroll
        for (int mi = 0; mi < 4; mi++)
            #pragma unroll
            for (int ni = 0; ni < 4; ni++) {
                int r  = m0 + wm0 + mi * 16 + (int)(lane >> 2);
                int ci = n0 + wn0 + ni * 8 + (int)((lane & 3) << 1);
                epi(bz, r,     ci, cc[mi][ni][0], cc[mi][ni][1]);
                epi(bz, r + 8, ci, cc[mi][ni][2], cc[mi][ni][3]);
            }
    }
}

// -------------------- prep: weights/biases to bf16 --------------------------
__global__ __launch_bounds__(256) void k_cvt_w(
    const float* __restrict__ tw, const float* __restrict__ pw, const float* __restrict__ gw,
    const float* __restrict__ tb, const float* __restrict__ pb, const float* __restrict__ gb,
    const float* __restrict__ ow)
{
    int i = blockIdx.x * 256 + threadIdx.x;
    const int W1 = CC * NPROJ, W2 = W1 + CHDIM * CC;
    if (i < W1) {
        int r = i / NPROJ, c = i % NPROJ;
        float v = (c < 64) ? tw[r * 64 + c] : (c < 128) ? pw[r * 64 + c - 64]
                                            : gw[r * 256 + c - 128];
        d_wcat[i] = __float2bfloat16(v);
    } else if (i < W2) {
        int j = i - W1;
        d_owbf[j] = __float2bfloat16(ow[j]);
    } else if (i < W2 + NPROJ) {
        int c = i - W2;
        d_bcat[c] = (c < 64) ? tb[c] : (c < 128) ? pb[c - 64] : gb[c - 128];
    }
}

// -------------------- 2x2 maxpool of phi+g (bf16) ---------------------------
__global__ __launch_bounds__(256) void k_pool2() {
    int idx = blockIdx.x * 256 + threadIdx.x;     // over BB*HWD*160 pairs
    if (idx >= BB * HWD * 160) return;
    int fp = idx % 160;
    int i  = (idx / 160) % HWD;
    int b  = idx / (160 * HWD);
    int h = i >> 5, w = i & 31;
    int col = 64 + fp * 2;                         // phi cols 64..127, g cols 128..383
    size_t rb = ((size_t)b * HW + (size_t)(2 * h) * WWID + 2 * w) * NPROJ + col;
    bf162 v0 = *(const bf162*)&d_projbf[rb];
    bf162 v1 = *(const bf162*)&d_projbf[rb + NPROJ];
    bf162 v2 = *(const bf162*)&d_projbf[rb + (size_t)WWID * NPROJ];
    bf162 v3 = *(const bf162*)&d_projbf[rb + (size_t)(WWID + 1) * NPROJ];
    float mx = fmaxf(fmaxf(__bfloat162float(v0.x), __bfloat162float(v1.x)),
                     fmaxf(__bfloat162float(v2.x), __bfloat162float(v3.x)));
    float my = fmaxf(fmaxf(__bfloat162float(v0.y), __bfloat162float(v1.y)),
                     fmaxf(__bfloat162float(v2.y), __bfloat162float(v3.y)));
    bf162 o; o.x = __float2bfloat16(mx); o.y = __float2bfloat16(my);
    int f0 = fp * 2;
    if (f0 < 64) *(bf162*)&d_phibf[((size_t)b * HWD + i) * CFG + f0] = o;
    else         *(bf162*)&d_gbf  [((size_t)b * HWD + i) * CHDIM + (f0 - 64)] = o;
}

// -------------------- Z reduce + g scaling ----------------------------------
__global__ __launch_bounds__(256) void k_zred() {
    int r = blockIdx.x * 256 + threadIdx.x;       // 8192 rows
    if (r >= BB * HWD) return;
    const float* p = &d_part[(size_t)r * 32];
    float z = 0.f;
    #pragma unroll
    for (int i = 0; i < 32; i++) z += p[i];
    d_invZ[r] = 1.0f / z;
}

__global__ __launch_bounds__(256) void k_gscale() {
    int idx = blockIdx.x * 256 + threadIdx.x;     // bf162 pairs: 8*1024*128
    if (idx >= BB * HWD * 128) return;
    int row = idx >> 7;                           // (b*1024 + i)
    float iz = d_invZ[row];
    bf162 v = *(bf162*)&d_gbf[(size_t)idx * 2];
    v.x = __float2bfloat16(__bfloat162float(v.x) * iz);
    v.y = __float2bfloat16(__bfloat162float(v.y) * iz);
    *(bf162*)&d_gbf[(size_t)idx * 2] = v;
}

// -------------------- launch -----------------------------------------------
extern "C" void kernel_launch(void* const* d_in, const int* in_sizes, int n_in,
                              void* d_out, int out_size)
{
    const float* x  = (const float*)d_in[0];
    const float* tw = (const float*)d_in[1];
    const float* tb = (const float*)d_in[2];
    const float* pw = (const float*)d_in[3];
    const float* pb = (const float*)d_in[4];
    const float* gw = (const float*)d_in[5];
    const float* gb = (const float*)d_in[6];
    const float* ow = (const float*)d_in[7];
    const float* ob = (const float*)d_in[8];
    const float* gm = (const float*)d_in[9];
    float* out = (float*)d_out;

    void *p_wcat, *p_owbf, *p_projbf, *p_phibf, *p_gbf, *p_ebf, *p_obf;
    cudaGetSymbolAddress(&p_wcat,  d_wcat);
    cudaGetSymbolAddress(&p_owbf,  d_owbf);
    cudaGetSymbolAddress(&p_projbf,d_projbf);
    cudaGetSymbolAddress(&p_phibf, d_phibf);
    cudaGetSymbolAddress(&p_gbf,   d_gbf);
    cudaGetSymbolAddress(&p_ebf,   d_ebf);
    cudaGetSymbolAddress(&p_obf,   d_obf);

    // prep: weights to bf16 (x converted on the fly inside proj GEMM)
    k_cvt_w<<<(CC * NPROJ + CHDIM * CC + NPROJ + 255) / 256, 256>>>(tw, pw, gw, tb, pb, gb, ow);

    // 1) projections: [32768,512]fp32 @ [512,384] -> bf16 proj
    gemm_bf16<false, false, true, false, EpiProj><<<dim3(NPROJ / 128, MROWS / 128, 1), 256>>>(
        x, (const bf16*)p_wcat, CC, NPROJ, CC, 0, 0, EpiProj{});

    // 2) 2x2 maxpool
    k_pool2<<<(BB * HWD * 160 + 255) / 256, 256>>>();

    // 3) e = exp(phi @ theta^T) per batch, + row partial sums
    gemm_bf16<false, true, false, true, EpiNone><<<dim3(HW / 128, HWD / 128, BB), 256>>>(
        p_phibf, (const bf16*)p_projbf, CFG, NPROJ, CFG,
        (size_t)HWD * CFG, (size_t)HW * NPROJ, EpiNone{});

    // 4) Z reduction; fold 1/Z into g rows
    k_zred  <<<(BB * HWD + 255) / 256, 256>>>();
    k_gscale<<<(BB * HWD * 128 + 255) / 256, 256>>>();

    // 5) o = e^T @ g' per batch: [4096,1024] @ [1024,256], A is [k][m]
    gemm_bf16<true, false, false, false, EpiO><<<dim3(CHDIM / 128, HW / 128, BB), 256>>>(
        p_ebf, (const bf16*)p_gbf, HW, CHDIM, HWD,
        (size_t)HWD * HW, (size_t)HWD * CHDIM, EpiO{});

    // 6) out = gamma*(o @ o3_w + b) + x: [32768,256] @ [256,512]
    EpiFinal ef{x, ob, gm, out};
    gemm_bf16<false, false, false, false, EpiFinal><<<dim3(CC / 128, MROWS / 128, 1), 256>>>(
        p_obf, (const bf16*)p_owbf, CHDIM, CC, CHDIM, 0, 0, ef);
}

// round 4
// speedup vs baseline: 4.8296x; 1.0022x over previous
#include <cuda_runtime.h>
#include <cuda_bf16.h>
#include <math.h>

// Problem dims (fixed)
#define BB    8
#define HH    64
#define WWID  64
#define CC    512
#define CFG   64
#define CHDIM 256
#define HW    4096
#define HWD   1024
#define MROWS 32768          // BB*HW
#define NPROJ 384            // CFG + CFG + CHDIM

typedef __nv_bfloat16 bf16;
typedef __nv_bfloat162 bf162;

// -------------------- device scratch (BSS, allocation-free) ----------------
__device__ bf16  d_wcat [(size_t)CC * NPROJ];         // [theta|phi|g] weights
__device__ bf16  d_owbf [(size_t)CHDIM * CC];         // o3 weights
__device__ float d_bcat [NPROJ];                      // [theta|phi|g] biases
__device__ bf16  d_projbf[(size_t)MROWS * NPROJ];     // projections pre-pool
__device__ bf16  d_phibf[(size_t)BB * HWD * CFG];
__device__ bf16  d_gbf  [(size_t)BB * HWD * CHDIM];   // pooled g, later scaled by 1/Z
__device__ bf16  d_ebf  [(size_t)BB * HWD * HW];      // e = exp(s), unnormalized
__device__ float d_part [(size_t)BB * HWD * 32];      // per-(row, jtile) partial sums
__device__ float d_invZ [(size_t)BB * HWD];           // 1/Z per softmax row
__device__ bf16  d_obf  [(size_t)MROWS * CHDIM];      // attention out

// -------------------- PTX helpers -----------------------------------------
__device__ __forceinline__ unsigned smem_u32(const void* p) {
    return (unsigned)__cvta_generic_to_shared(p);
}
__device__ __forceinline__ void ldsm_x4(unsigned a[4], unsigned addr) {
    asm volatile("ldmatrix.sync.aligned.m8n8.x4.shared.b16 {%0,%1,%2,%3}, [%4];"
        : "=r"(a[0]), "=r"(a[1]), "=r"(a[2]), "=r"(a[3]) : "r"(addr));
}
__device__ __forceinline__ void ldsm_x4_t(unsigned a[4], unsigned addr) {
    asm volatile("ldmatrix.sync.aligned.m8n8.x4.trans.shared.b16 {%0,%1,%2,%3}, [%4];"
        : "=r"(a[0]), "=r"(a[1]), "=r"(a[2]), "=r"(a[3]) : "r"(addr));
}
__device__ __forceinline__ void ldsm_x2(unsigned b[2], unsigned addr) {
    asm volatile("ldmatrix.sync.aligned.m8n8.x2.shared.b16 {%0,%1}, [%2];"
        : "=r"(b[0]), "=r"(b[1]) : "r"(addr));
}
__device__ __forceinline__ void ldsm_x2_t(unsigned b[2], unsigned addr) {
    asm volatile("ldmatrix.sync.aligned.m8n8.x2.trans.shared.b16 {%0,%1}, [%2];"
        : "=r"(b[0]), "=r"(b[1]) : "r"(addr));
}
__device__ __forceinline__ void mma16816(float c[4], const unsigned a[4], const unsigned b[2]) {
    asm volatile(
        "mma.sync.aligned.m16n8k16.row.col.f32.bf16.bf16.f32 "
        "{%0,%1,%2,%3}, {%4,%5,%6,%7}, {%8,%9}, {%0,%1,%2,%3};"
        : "+f"(c[0]), "+f"(c[1]), "+f"(c[2]), "+f"(c[3])
        : "r"(a[0]), "r"(a[1]), "r"(a[2]), "r"(a[3]), "r"(b[0]), "r"(b[1]));
}

// -------------------- epilogue functors ------------------------------------
struct EpiNone {
    __device__ void operator()(int, int, int, float, float) const {}
};
struct EpiProj {  // bf16 out, add bias from d_bcat
    __device__ void operator()(int, int r, int c, float v0, float v1) const {
        bf162 p;
        p.x = __float2bfloat16(v0 + d_bcat[c]);
        p.y = __float2bfloat16(v1 + d_bcat[c + 1]);
        *(bf162*)&d_projbf[(size_t)r * NPROJ + c] = p;
    }
};
struct EpiO {     // bf16 attention out
    __device__ void operator()(int b, int r, int c, float v0, float v1) const {
        bf162 p; p.x = __float2bfloat16(v0); p.y = __float2bfloat16(v1);
        *(bf162*)&d_obf[((size_t)b * HW + r) * CHDIM + c] = p;
    }
};
struct EpiFinal { // out = gamma*(acc+bias) + x, fp32
    const float* x; const float* ob; const float* gm; float* out;
    __device__ void operator()(int, int r, int c, float v0, float v1) const {
        float g = gm[0];
        size_t off = (size_t)r * CC + c;
        float2 xv = *(const float2*)&x[off];
        float2 o;
        o.x = g * (v0 + ob[c])     + xv.x;
        o.y = g * (v1 + ob[c + 1]) + xv.y;
        *(float2*)&out[off] = o;
    }
};

// -------------------- templated bf16 GEMM ----------------------------------
// C[M,N] (+epi) = A @ B.  Block tile 128x128x32, 8 warps (2x4), warp 64x32.
// AKM=false: A[m][k] (k contig).  AKM=true: A[k][m] (m contig).
// BNK=false: B[k][n] (n contig).  BNK=true: B[n][k] (k contig).
// AF32: A is fp32 in gmem (MK layout only), converted to bf16 into smem.
// SEPI: softmax-exp epilogue (writes e=exp(acc) bf16 to d_ebf + row partials).
template<bool AKM, bool BNK, bool AF32, bool SEPI, class Epi>
__global__ __launch_bounds__(256, 2) void gemm_bf16(
    const void* __restrict__ Av, const bf16* __restrict__ B,
    int lda, int ldb, int K, size_t bsA, size_t bsB, Epi epi)
{
    constexpr int AST = AKM ? 136 : 40;   // smem row stride (halves), padded
    constexpr int ASZ = AKM ? 32 * 136 : 128 * 40;
    constexpr int BST = BNK ? 40 : 136;
    constexpr int BSZ = BNK ? 128 * 40 : 32 * 136;
    __shared__ __align__(16) bf16 As[ASZ];
    __shared__ __align__(16) bf16 Bs[BSZ];
    __shared__ float rs[128][4];          // SEPI row partial sums

    const bf16*  A   = (const bf16*)Av;
    const float* A32 = (const float*)Av;
    const int bz = blockIdx.z;
    A   += (size_t)bz * bsA;
    B   += (size_t)bz * bsB;
    const int m0 = blockIdx.y * 128, n0 = blockIdx.x * 128;

    const int t = threadIdx.x;
    const unsigned lane = t & 31;
    const int w = t >> 5;
    const int wm0 = (w >> 2) * 64;     // warp row offset in tile
    const int wn0 = (w & 3) * 32;      // warp col offset in tile

    uint4 ra[2], rb[2];
    auto ldA = [&](int k0) {
        #pragma unroll
        for (int it = 0; it < 2; it++) {
            int e = it * 256 + t;
            if (AF32) {
                int r = e >> 2, c = (e & 3) << 3;
                const float* p = A32 + (size_t)(m0 + r) * lda + k0 + c;
                float4 f0 = *(const float4*)p;
                float4 f1 = *(const float4*)(p + 4);
                bf162 h0 = __float22bfloat162_rn(make_float2(f0.x, f0.y));
                bf162 h1 = __float22bfloat162_rn(make_float2(f0.z, f0.w));
                bf162 h2 = __float22bfloat162_rn(make_float2(f1.x, f1.y));
                bf162 h3 = __float22bfloat162_rn(make_float2(f1.z, f1.w));
                ra[it].x = *(unsigned*)&h0; ra[it].y = *(unsigned*)&h1;
                ra[it].z = *(unsigned*)&h2; ra[it].w = *(unsigned*)&h3;
            } else if (!AKM) {
                int r = e >> 2, c = (e & 3) << 3;
                ra[it] = *(const uint4*)(A + (size_t)(m0 + r) * lda + k0 + c);
            } else {
                int r = e >> 4, c = (e & 15) << 3;
                ra[it] = *(const uint4*)(A + (size_t)(k0 + r) * lda + m0 + c);
            }
        }
    };
    auto ldB = [&](int k0) {
        #pragma unroll
        for (int it = 0; it < 2; it++) {
            int e = it * 256 + t;
            if (BNK) { int r = e >> 2, c = (e & 3) << 3;
                rb[it] = *(const uint4*)(B + (size_t)(n0 + r) * ldb + k0 + c); }
            else     { int r = e >> 4, c = (e & 15) << 3;
                rb[it] = *(const uint4*)(B + (size_t)(k0 + r) * ldb + n0 + c); }
        }
    };
    auto stAB = [&]() {
        #pragma unroll
        for (int it = 0; it < 2; it++) {
            int e = it * 256 + t;
            if (!AKM) { int r = e >> 2, c = (e & 3) << 3; *(uint4*)&As[r * 40 + c] = ra[it]; }
            else      { int r = e >> 4, c = (e & 15) << 3; *(uint4*)&As[r * 136 + c] = ra[it]; }
            if (BNK)  { int r = e >> 2, c = (e & 3) << 3; *(uint4*)&Bs[r * 40 + c] = rb[it]; }
            else      { int r = e >> 4, c = (e & 15) << 3; *(uint4*)&Bs[r * 136 + c] = rb[it]; }
        }
    };

    float cc[4][4][4] = {};
    const unsigned asb = smem_u32(As), bsb = smem_u32(Bs);

    ldA(0); ldB(0);
    stAB();
    __syncthreads();

    for (int k0 = 0; k0 < K; k0 += 32) {
        const bool more = (k0 + 32 < K);
        if (more) { ldA(k0 + 32); ldB(k0 + 32); }

        #pragma unroll
        for (int ks = 0; ks < 2; ks++) {
            const int kk = ks * 16;
            unsigned afr[4][4];
            #pragma unroll
            for (int mi = 0; mi < 4; mi++) {
                unsigned addr;
                if (!AKM) {
                    addr = asb + (unsigned)(((wm0 + mi * 16 + (lane & 15)) * AST
                                  + kk + ((lane >> 4) << 3)) * 2);
                    ldsm_x4(afr[mi], addr);
                } else {
                    addr = asb + (unsigned)(((kk + (lane & 7) + ((lane >> 4) << 3)) * AST
                                  + wm0 + mi * 16 + (((lane >> 3) & 1) << 3)) * 2);
                    ldsm_x4_t(afr[mi], addr);
                }
            }
            unsigned bfr[4][2];
            #pragma unroll
            for (int ni = 0; ni < 4; ni++) {
                unsigned addr;
                if (!BNK) {
                    addr = bsb + (unsigned)(((kk + (lane & 15)) * BST + wn0 + ni * 8) * 2);
                    ldsm_x2_t(bfr[ni], addr);
                } else {
                    addr = bsb + (unsigned)(((wn0 + ni * 8 + (lane & 7)) * BST
                                  + kk + (((lane >> 3) & 1) << 3)) * 2);
                    ldsm_x2(bfr[ni], addr);
                }
            }
            #pragma unroll
            for (int mi = 0; mi < 4; mi++)
                #pragma unroll
                for (int ni = 0; ni < 4; ni++)
                    mma16816(cc[mi][ni], afr[mi], bfr[ni]);
        }

        __syncthreads();
        if (more) { stAB(); __syncthreads(); }
    }

    if constexpr (SEPI) {
        // e = exp(acc), write bf16, accumulate deterministic row partial sums
        #pragma unroll
        for (int mi = 0; mi < 4; mi++) {
            float rp0 = 0.f, rp1 = 0.f;
            const int r = m0 + wm0 + mi * 16 + (int)(lane >> 2);
            #pragma unroll
            for (int ni = 0; ni < 4; ni++) {
                const int ci = n0 + wn0 + ni * 8 + (int)((lane & 3) << 1);
                float e0 = __expf(cc[mi][ni][0]), e1 = __expf(cc[mi][ni][1]);
                float e2 = __expf(cc[mi][ni][2]), e3 = __expf(cc[mi][ni][3]);
                bf162 p; p.x = __float2bfloat16(e0); p.y = __float2bfloat16(e1);
                *(bf162*)&d_ebf[((size_t)bz * HWD + r) * HW + ci] = p;
                bf162 q; q.x = __float2bfloat16(e2); q.y = __float2bfloat16(e3);
                *(bf162*)&d_ebf[((size_t)bz * HWD + r + 8) * HW + ci] = q;
                rp0 += e0 + e1; rp1 += e2 + e3;
            }
            rp0 += __shfl_xor_sync(0xffffffffu, rp0, 1);
            rp0 += __shfl_xor_sync(0xffffffffu, rp0, 2);
            rp1 += __shfl_xor_sync(0xffffffffu, rp1, 1);
            rp1 += __shfl_xor_sync(0xffffffffu, rp1, 2);
            if ((lane & 3) == 0) {
                int rl = wm0 + mi * 16 + (int)(lane >> 2);
                rs[rl][w & 3]     = rp0;
                rs[rl + 8][w & 3] = rp1;
            }
        }
        __syncthreads();
        if (t < 128) {
            float z = (rs[t][0] + rs[t][1]) + (rs[t][2] + rs[t][3]);
            d_part[((size_t)bz * HWD + m0 + t) * 32 + blockIdx.x] = z;
        }
    } else {
        #pragma unroll
        for (int mi = 0; mi < 4; mi++)
            #pragma unroll
            for (int ni = 0; ni < 4; ni++) {
                int r  = m0 + wm0 + mi * 16 + (int)(lane >> 2);
                int ci = n0 + wn0 + ni * 8 + (int)((lane & 3) << 1);
                epi(bz, r,     ci, cc[mi][ni][0], cc[mi][ni][1]);
                epi(bz, r + 8, ci, cc[mi][ni][2], cc[mi][ni][3]);
            }
    }
}

// -------------------- prep: weights/biases to bf16 --------------------------
__global__ __launch_bounds__(256) void k_cvt_w(
    const float* __restrict__ tw, const float* __restrict__ pw, const float* __restrict__ gw,
    const float* __restrict__ tb, const float* __restrict__ pb, const float* __restrict__ gb,
    const float* __restrict__ ow)
{
    int i = blockIdx.x * 256 + threadIdx.x;
    const int W1 = CC * NPROJ, W2 = W1 + CHDIM * CC;
    if (i < W1) {
        int r = i / NPROJ, c = i % NPROJ;
        float v = (c < 64) ? tw[r * 64 + c] : (c < 128) ? pw[r * 64 + c - 64]
                                            : gw[r * 256 + c - 128];
        d_wcat[i] = __float2bfloat16(v);
    } else if (i < W2) {
        int j = i - W1;
        d_owbf[j] = __float2bfloat16(ow[j]);
    } else if (i < W2 + NPROJ) {
        int c = i - W2;
        d_bcat[c] = (c < 64) ? tb[c] : (c < 128) ? pb[c - 64] : gb[c - 128];
    }
}

// -------------------- 2x2 maxpool of phi+g (bf16) ---------------------------
__global__ __launch_bounds__(256) void k_pool2() {
    int idx = blockIdx.x * 256 + threadIdx.x;     // over BB*HWD*160 pairs
    if (idx >= BB * HWD * 160) return;
    int fp = idx % 160;
    int i  = (idx / 160) % HWD;
    int b  = idx / (160 * HWD);
    int h = i >> 5, w = i & 31;
    int col = 64 + fp * 2;                         // phi cols 64..127, g cols 128..383
    size_t rb = ((size_t)b * HW + (size_t)(2 * h) * WWID + 2 * w) * NPROJ + col;
    bf162 v0 = *(const bf162*)&d_projbf[rb];
    bf162 v1 = *(const bf162*)&d_projbf[rb + NPROJ];
    bf162 v2 = *(const bf162*)&d_projbf[rb + (size_t)WWID * NPROJ];
    bf162 v3 = *(const bf162*)&d_projbf[rb + (size_t)(WWID + 1) * NPROJ];
    float mx = fmaxf(fmaxf(__bfloat162float(v0.x), __bfloat162float(v1.x)),
                     fmaxf(__bfloat162float(v2.x), __bfloat162float(v3.x)));
    float my = fmaxf(fmaxf(__bfloat162float(v0.y), __bfloat162float(v1.y)),
                     fmaxf(__bfloat162float(v2.y), __bfloat162float(v3.y)));
    bf162 o; o.x = __float2bfloat16(mx); o.y = __float2bfloat16(my);
    int f0 = fp * 2;
    if (f0 < 64) *(bf162*)&d_phibf[((size_t)b * HWD + i) * CFG + f0] = o;
    else         *(bf162*)&d_gbf  [((size_t)b * HWD + i) * CHDIM + (f0 - 64)] = o;
}

// -------------------- Z reduce + g scaling ----------------------------------
__global__ __launch_bounds__(256) void k_zred() {
    int r = blockIdx.x * 256 + threadIdx.x;       // 8192 rows
    if (r >= BB * HWD) return;
    const float* p = &d_part[(size_t)r * 32];
    float z = 0.f;
    #pragma unroll
    for (int i = 0; i < 32; i++) z += p[i];
    d_invZ[r] = 1.0f / z;
}

__global__ __launch_bounds__(256) void k_gscale() {
    int idx = blockIdx.x * 256 + threadIdx.x;     // bf162 pairs: 8*1024*128
    if (idx >= BB * HWD * 128) return;
    int row = idx >> 7;                           // (b*1024 + i)
    float iz = d_invZ[row];
    bf162 v = *(bf162*)&d_gbf[(size_t)idx * 2];
    v.x = __float2bfloat16(__bfloat162float(v.x) * iz);
    v.y = __float2bfloat16(__bfloat162float(v.y) * iz);
    *(bf162*)&d_gbf[(size_t)idx * 2] = v;
}

// -------------------- launch -----------------------------------------------
extern "C" void kernel_launch(void* const* d_in, const int* in_sizes, int n_in,
                              void* d_out, int out_size)
{
    const float* x  = (const float*)d_in[0];
    const float* tw = (const float*)d_in[1];
    const float* tb = (const float*)d_in[2];
    const float* pw = (const float*)d_in[3];
    const float* pb = (const float*)d_in[4];
    const float* gw = (const float*)d_in[5];
    const float* gb = (const float*)d_in[6];
    const float* ow = (const float*)d_in[7];
    const float* ob = (const float*)d_in[8];
    const float* gm = (const float*)d_in[9];
    float* out = (float*)d_out;

    void *p_wcat, *p_owbf, *p_projbf, *p_phibf, *p_gbf, *p_ebf, *p_obf;
    cudaGetSymbolAddress(&p_wcat,  d_wcat);
    cudaGetSymbolAddress(&p_owbf,  d_owbf);
    cudaGetSymbolAddress(&p_projbf,d_projbf);
    cudaGetSymbolAddress(&p_phibf, d_phibf);
    cudaGetSymbolAddress(&p_gbf,   d_gbf);
    cudaGetSymbolAddress(&p_ebf,   d_ebf);
    cudaGetSymbolAddress(&p_obf,   d_obf);

    // prep: weights to bf16 (x converted on the fly inside proj GEMM)
    k_cvt_w<<<(CC * NPROJ + CHDIM * CC + NPROJ + 255) / 256, 256>>>(tw, pw, gw, tb, pb, gb, ow);

    // 1) projections: [32768,512]fp32 @ [512,384] -> bf16 proj
    gemm_bf16<false, false, true, false, EpiProj><<<dim3(NPROJ / 128, MROWS / 128, 1), 256>>>(
        x, (const bf16*)p_wcat, CC, NPROJ, CC, 0, 0, EpiProj{});

    // 2) 2x2 maxpool
    k_pool2<<<(BB * HWD * 160 + 255) / 256, 256>>>();

    // 3) e = exp(phi @ theta^T) per batch, + row partial sums
    gemm_bf16<false, true, false, true, EpiNone><<<dim3(HW / 128, HWD / 128, BB), 256>>>(
        p_phibf, (const bf16*)p_projbf, CFG, NPROJ, CFG,
        (size_t)HWD * CFG, (size_t)HW * NPROJ, EpiNone{});

    // 4) Z reduction; fold 1/Z into g rows
    k_zred  <<<(BB * HWD + 255) / 256, 256>>>();
    k_gscale<<<(BB * HWD * 128 + 255) / 256, 256>>>();

    // 5) o = e^T @ g' per batch: [4096,1024] @ [1024,256], A is [k][m]
    gemm_bf16<true, false, false, false, EpiO><<<dim3(CHDIM / 128, HW / 128, BB), 256>>>(
        p_ebf, (const bf16*)p_gbf, HW, CHDIM, HWD,
        (size_t)HWD * HW, (size_t)HWD * CHDIM, EpiO{});

    // 6) out = gamma*(o @ o3_w + b) + x: [32768,256] @ [256,512]
    EpiFinal ef{x, ob, gm, out};
    gemm_bf16<false, false, false, false, EpiFinal><<<dim3(CC / 128, MROWS / 128, 1), 256>>>(
        p_obf, (const bf16*)p_owbf, CHDIM, CC, CHDIM, 0, 0, ef);
}